// round 4
// baseline (speedup 1.0000x reference)
#include <cuda_runtime.h>
#include <cuda_bf16.h>

#define DNF  133
#define DPAD 136   // padded feature stride: 544 B rows, float4-aligned
#define MAXN 50000
#define MAXE 800000
#define NGRAPH 256

// ---------------- static device scratch (zero-initialized at load) ----------------
__device__ float g_hp[MAXN * DPAD];    // (X@W) * dinv[row]; cols 133..135 stay 0
__device__ float g_feat[MAXN * DPAD];  // layer outputs;     cols 133..135 stay 0
__device__ int   g_deg[MAXN];
__device__ float g_dinv[MAXN];
__device__ int   g_rowptr[MAXN + 1];
__device__ int   g_pos[MAXN];
__device__ int   g_col[MAXE];
__device__ int   g_is64;               // 1 if edge_index/batch are int64

// ---------------- packed f32x2 helpers (sm_10x; ptxas won't auto-fuse) ----------------
#define FMA2(acc, a, b) \
    asm("fma.rn.f32x2 %0, %1, %2, %3;" : "=l"(acc) : "l"(a), "l"(b), "l"(acc))
#define PACK2(d, lo, hi) \
    asm("mov.b64 %0, {%1, %2};" : "=l"(d) : "f"(lo), "f"(hi))
#define UNPACK2(lo, hi, s) \
    asm("mov.b64 {%0, %1}, %2;" : "=f"(lo), "=f"(hi) : "l"(s))

// ---------------- dtype detection (warp-parallel, no serial chain) ----------------
// int64 values < 2^31 -> every odd int32 word is 0. int32 random ids -> not.
__global__ void detect_kernel(const int* __restrict__ w) {
    int lane = threadIdx.x & 31;
    int bad = 0;
#pragma unroll
    for (int it = 0; it < 32; it++)
        bad |= w[2 * (lane + 32 * it) + 1];
    unsigned any = __ballot_sync(0xffffffffu, bad != 0);
    if (lane == 0) g_is64 = (any == 0u) ? 1 : 0;
}

__device__ __forceinline__ int load_idx(const void* p, long long i) {
    return g_is64 ? (int)((const long long*)p)[i] : ((const int*)p)[i];
}

// ---------------- CSR build ----------------
__global__ void init_deg_kernel(int n) {
    int i = blockIdx.x * blockDim.x + threadIdx.x;
    if (i < n) g_deg[i] = 1;  // self-loop
}

__global__ void count_deg_kernel(const void* __restrict__ ei, int e) {
    int i = blockIdx.x * blockDim.x + threadIdx.x;
    if (i < e) atomicAdd(&g_deg[load_idx(ei, (long long)e + i)], 1);
}

// Exclusive scan of (deg-1) into rowptr; also writes pos (=rowptr) and dinv.
__global__ void scan_kernel(int n) {
    __shared__ int psum[512];
    int t = threadIdx.x;
    int chunk = (n + 511) / 512;
    int begin = t * chunk;
    int end = begin + chunk; if (end > n) end = n;
    int s = 0;
    for (int i = begin; i < end; i++) s += g_deg[i] - 1;
    psum[t] = s;
    __syncthreads();
    __shared__ int total_s;
    if (t == 0) {
        int running = 0;
        for (int i = 0; i < 512; i++) { int v = psum[i]; psum[i] = running; running += v; }
        total_s = running;
    }
    __syncthreads();
    int run = psum[t];
    for (int i = begin; i < end; i++) {
        int d = g_deg[i];
        g_rowptr[i] = run;
        g_pos[i] = run;
        g_dinv[i] = rsqrtf((float)d);
        run += d - 1;
    }
    if (t == 0) g_rowptr[n] = total_s;
}

__global__ void fill_kernel(const void* __restrict__ ei, int e) {
    int i = blockIdx.x * blockDim.x + threadIdx.x;
    if (i < e) {
        int sidx = load_idx(ei, i);
        int d    = load_idx(ei, (long long)e + i);
        g_col[atomicAdd(&g_pos[d], 1)] = sidx;
    }
}

// ---------------- GEMM: g_hp[r][c] = dinv[r] * sum_k X[r][k]*W[k][c] ----------------
// 256 threads/block, 64 rows x 133 cols, K tiled by 32.
// f32x2 packing over ROW PAIRS: X tile stored transposed (k-major) so a row-pair
// is one aligned 8-byte smem load; b replicated into both halves once per (k,j).
// Thread (warp w, lane l): row-pairs w*8+{0,2,4,6}, cols l+32*j (j<5).
__global__ void gemm_scale_kernel(const float* __restrict__ Xext,
                                  const float* __restrict__ W,
                                  int use_ext, int n) {
    __shared__ float Ws[32][DNF + 3];   // [kk][col]
    __shared__ float Xs[32][66];        // [kk][row] transposed; pad 66 keeps f2 aligned

    const float* X = use_ext ? Xext : (const float*)g_feat;
    int ldx = use_ext ? DNF : DPAD;
    int tid = threadIdx.x;
    int lane = tid & 31, warp = tid >> 5;
    int row0 = blockIdx.x * 64;
    int rbase = warp * 8;

    unsigned long long acc[4][5];
#pragma unroll
    for (int i = 0; i < 4; i++)
#pragma unroll
        for (int j = 0; j < 5; j++) acc[i][j] = 0ull;

    for (int k0 = 0; k0 < DNF; k0 += 32) {
        int kc = DNF - k0; if (kc > 32) kc = 32;

        for (int i = tid; i < kc * DNF; i += 256) {
            int kk = i / DNF, c = i - kk * DNF;
            Ws[kk][c] = W[(k0 + kk) * DNF + c];
        }
        // transposed X tile: consecutive tid -> consecutive kk -> coalesced gmem
        for (int i = tid; i < 64 * 32; i += 256) {
            int kk = i & 31, r = i >> 5;
            int gr = row0 + r;
            Xs[kk][r] = (kk < kc && gr < n) ? X[(size_t)gr * ldx + k0 + kk] : 0.f;
        }
        __syncthreads();

        for (int kk = 0; kk < kc; kk++) {
            float b[5];
#pragma unroll
            for (int j = 0; j < 4; j++) b[j] = Ws[kk][lane + 32 * j];
            b[4] = (lane < 5) ? Ws[kk][lane + 128] : 0.f;
            unsigned long long b2[5];
#pragma unroll
            for (int j = 0; j < 5; j++) PACK2(b2[j], b[j], b[j]);
            unsigned long long a2[4];
#pragma unroll
            for (int i = 0; i < 4; i++)
                a2[i] = *reinterpret_cast<const unsigned long long*>(&Xs[kk][rbase + 2 * i]);
#pragma unroll
            for (int i = 0; i < 4; i++)
#pragma unroll
                for (int j = 0; j < 5; j++) FMA2(acc[i][j], a2[i], b2[j]);
        }
        __syncthreads();
    }

#pragma unroll
    for (int i = 0; i < 4; i++) {
        int r0 = row0 + rbase + 2 * i;
        int r1 = r0 + 1;
        float d0 = (r0 < n) ? g_dinv[r0] : 0.f;
        float d1 = (r1 < n) ? g_dinv[r1] : 0.f;
#pragma unroll
        for (int j = 0; j < 5; j++) {
            int c = lane + 32 * j;
            float lo, hi;
            UNPACK2(lo, hi, acc[i][j]);
            if (c < DNF) {
                if (r0 < n) g_hp[(size_t)r0 * DPAD + c] = lo * d0;
                if (r1 < n) g_hp[(size_t)r1 * DPAD + c] = hi * d1;
            }
        }
    }
}

// ---------------- aggregate: g_feat[i] = relu(dinv[i]*(sum_in hp[j] + hp[i]) + b) ----------------
// One warp per node; lane owns float4 at col 4*lane; lanes 0..1 also own the
// tail float4s at cols 128..135 (pads 133..135 are zero in g_hp).
__global__ void aggregate_kernel(const float* __restrict__ bias, int n) {
    int node = blockIdx.x * (blockDim.x >> 5) + (threadIdx.x >> 5);
    if (node >= n) return;
    int lane = threadIdx.x & 31;

    const float4* self4 = (const float4*)(g_hp + (size_t)node * DPAD);
    float4 acc = self4[lane];
    float4 acct = make_float4(0.f, 0.f, 0.f, 0.f);
    if (lane < 2) acct = self4[32 + lane];

    int s = g_rowptr[node], e = g_rowptr[node + 1];
    int idx = s;
    for (; idx + 1 < e; idx += 2) {
        int j0 = g_col[idx], j1 = g_col[idx + 1];
        const float4* r0 = (const float4*)(g_hp + (size_t)j0 * DPAD);
        const float4* r1 = (const float4*)(g_hp + (size_t)j1 * DPAD);
        float4 v0 = r0[lane];
        float4 v1 = r1[lane];
        float4 t0, t1;
        if (lane < 2) { t0 = r0[32 + lane]; t1 = r1[32 + lane]; }
        acc.x += v0.x; acc.y += v0.y; acc.z += v0.z; acc.w += v0.w;
        acc.x += v1.x; acc.y += v1.y; acc.z += v1.z; acc.w += v1.w;
        if (lane < 2) {
            acct.x += t0.x; acct.y += t0.y; acct.z += t0.z; acct.w += t0.w;
            acct.x += t1.x; acct.y += t1.y; acct.z += t1.z; acct.w += t1.w;
        }
    }
    if (idx < e) {
        int j0 = g_col[idx];
        const float4* r0 = (const float4*)(g_hp + (size_t)j0 * DPAD);
        float4 v0 = r0[lane];
        acc.x += v0.x; acc.y += v0.y; acc.z += v0.z; acc.w += v0.w;
        if (lane < 2) {
            float4 t0 = r0[32 + lane];
            acct.x += t0.x; acct.y += t0.y; acct.z += t0.z; acct.w += t0.w;
        }
    }

    float di = g_dinv[node];
    float4 o;
    o.x = fmaxf(fmaf(acc.x, di, bias[4 * lane + 0]), 0.f);
    o.y = fmaxf(fmaf(acc.y, di, bias[4 * lane + 1]), 0.f);
    o.z = fmaxf(fmaf(acc.z, di, bias[4 * lane + 2]), 0.f);
    o.w = fmaxf(fmaf(acc.w, di, bias[4 * lane + 3]), 0.f);
    float4* out4 = (float4*)(g_feat + (size_t)node * DPAD);
    out4[lane] = o;
    if (lane == 0) {
        float4 t;
        t.x = fmaxf(fmaf(acct.x, di, bias[128]), 0.f);
        t.y = fmaxf(fmaf(acct.y, di, bias[129]), 0.f);
        t.z = fmaxf(fmaf(acct.z, di, bias[130]), 0.f);
        t.w = fmaxf(fmaf(acct.w, di, bias[131]), 0.f);
        out4[32] = t;
    } else if (lane == 1) {
        float4 t;
        t.x = fmaxf(fmaf(acct.x, di, bias[132]), 0.f);
        t.y = 0.f; t.z = 0.f; t.w = 0.f;   // keep pads zero
        out4[33] = t;
    }
}

// ---------------- global mean pool ----------------
__device__ __forceinline__ int lbound_any(const void* a, int n, int v) {
    int lo = 0, hi = n;
    while (lo < hi) {
        int m = (lo + hi) >> 1;
        long long x = g_is64 ? ((const long long*)a)[m]
                             : (long long)((const int*)a)[m];
        if (x < (long long)v) lo = m + 1; else hi = m;
    }
    return lo;
}

__global__ void pool_kernel(const void* __restrict__ batch,
                            float* __restrict__ out, int n) {
    __shared__ int lo_s, hi_s;
    int g = blockIdx.x;
    if (threadIdx.x == 0) {
        lo_s = lbound_any(batch, n, g);
        hi_s = lbound_any(batch, n, g + 1);
    }
    __syncthreads();
    int lo = lo_s, hi = hi_s;
    int c = threadIdx.x;
    if (c < DNF) {
        float s0 = 0.f, s1 = 0.f, s2 = 0.f, s3 = 0.f;
        int r = lo;
        for (; r + 3 < hi; r += 4) {
            s0 += g_feat[(size_t)(r + 0) * DPAD + c];
            s1 += g_feat[(size_t)(r + 1) * DPAD + c];
            s2 += g_feat[(size_t)(r + 2) * DPAD + c];
            s3 += g_feat[(size_t)(r + 3) * DPAD + c];
        }
        for (; r < hi; r++) s0 += g_feat[(size_t)r * DPAD + c];
        int cnt = hi - lo;
        out[g * DNF + c] = ((s0 + s1) + (s2 + s3)) / (float)(cnt > 0 ? cnt : 1);
    }
}

// ---------------- launch: kernel launches ONLY ----------------
extern "C" void kernel_launch(void* const* d_in, const int* in_sizes, int n_in,
                              void* d_out, int out_size) {
    const float* x     = (const float*)d_in[0];
    const void*  ei    = d_in[1];
    const void*  batch = d_in[2];
    const float* W1    = (const float*)d_in[3];
    const float* b1    = (const float*)d_in[4];
    const float* W2    = (const float*)d_in[5];
    const float* b2    = (const float*)d_in[6];
    float* out = (float*)d_out;

    int n = in_sizes[0] / DNF;   // 50000
    int e = in_sizes[1] / 2;     // 800000

    int tb = 256;
    int gn = (n + tb - 1) / tb;
    int ge = (e + tb - 1) / tb;

    detect_kernel<<<1, 32>>>((const int*)ei);        // launch 1
    init_deg_kernel<<<gn, tb>>>(n);                  // launch 2
    count_deg_kernel<<<ge, tb>>>(ei, e);             // launch 3
    scan_kernel<<<1, 512>>>(n);                      // launch 4 (rowptr+pos+dinv)
    fill_kernel<<<ge, tb>>>(ei, e);                  // launch 5

    int gemm_blocks = (n + 63) / 64;
    int agg_blocks  = (n + 7) / 8;

    gemm_scale_kernel<<<gemm_blocks, 256>>>(x, W1, 1, n);  // launch 6 <- ncu -s 5 -c 1
    aggregate_kernel<<<agg_blocks, 256>>>(b1, n);
    gemm_scale_kernel<<<gemm_blocks, 256>>>(x, W2, 0, n);
    aggregate_kernel<<<agg_blocks, 256>>>(b2, n);

    pool_kernel<<<NGRAPH, 160>>>(batch, out, n);
}

// round 5
// speedup vs baseline: 1.2673x; 1.2673x over previous
#include <cuda_runtime.h>
#include <cuda_bf16.h>

#define DNF  133
#define DPAD 136   // padded feature stride: 544 B rows, float4-aligned
#define MAXN 50000
#define MAXE 800000
#define NGRAPH 256

// ---------------- static device scratch (zero-initialized at load) ----------------
__device__ float g_hp[MAXN * DPAD];    // (X@W) * dinv[row]; cols 133..135 stay 0
__device__ float g_feat[MAXN * DPAD];  // layer outputs;     cols 133..135 stay 0
__device__ int   g_deg[MAXN];
__device__ float g_dinv[MAXN];
__device__ int   g_rowptr[MAXN + 1];
__device__ int   g_pos[MAXN];
__device__ int   g_col[MAXE];
__device__ int   g_bsum[256];          // per-block edge-count sums (196 used)
__device__ int   g_is64;               // 1 if edge_index/batch are int64

// ---------------- prologue: deg=1 (self loop) + dtype detect ----------------
// int64 values < 2^31 -> every odd int32 word is 0. int32 random ids -> not.
__global__ void prologue_kernel(const int* __restrict__ w, int n) {
    int i = blockIdx.x * blockDim.x + threadIdx.x;
    if (i < n) g_deg[i] = 1;
    if (blockIdx.x == 0 && threadIdx.x < 32) {
        int lane = threadIdx.x;
        int bad = 0;
#pragma unroll
        for (int it = 0; it < 32; it++)
            bad |= w[2 * (lane + 32 * it) + 1];
        unsigned any = __ballot_sync(0xffffffffu, bad != 0);
        if (lane == 0) g_is64 = (any == 0u) ? 1 : 0;
    }
}

__device__ __forceinline__ int load_idx(const void* p, long long i) {
    return g_is64 ? (int)((const long long*)p)[i] : ((const int*)p)[i];
}

__global__ void count_deg_kernel(const void* __restrict__ ei, int e) {
    int i = blockIdx.x * blockDim.x + threadIdx.x;
    if (i < e) atomicAdd(&g_deg[load_idx(ei, (long long)e + i)], 1);
}

// ---------------- 2-level parallel exclusive scan of (deg-1) ----------------
__global__ void partial_kernel(int n) {
    __shared__ int wsum[8];
    int i = blockIdx.x * blockDim.x + threadIdx.x;
    int d = (i < n) ? g_deg[i] - 1 : 0;
    int lane = threadIdx.x & 31, wid = threadIdx.x >> 5;
#pragma unroll
    for (int o = 16; o > 0; o >>= 1) d += __shfl_down_sync(0xffffffffu, d, o);
    if (lane == 0) wsum[wid] = d;
    __syncthreads();
    if (wid == 0) {
        int s = (lane < 8) ? wsum[lane] : 0;
#pragma unroll
        for (int o = 4; o > 0; o >>= 1) s += __shfl_down_sync(0xffffffffu, s, o);
        if (lane == 0) g_bsum[blockIdx.x] = s;
    }
}

// Each block: offset = sum(bsum[0..bid)), local exclusive scan of its 256 nodes,
// then write rowptr/pos/dinv. rowptr[n] = e analytically.
__global__ void finalize_kernel(int n, int e) {
    __shared__ int wsum[8];
    __shared__ int off_s;
    int tid = threadIdx.x, bid = blockIdx.x;
    int lane = tid & 31, wid = tid >> 5;

    // block offset: reduce bsum[tid] for tid < bid
    {
        int v = (tid < bid) ? g_bsum[tid] : 0;
#pragma unroll
        for (int o = 16; o > 0; o >>= 1) v += __shfl_down_sync(0xffffffffu, v, o);
        if (lane == 0) wsum[wid] = v;
        __syncthreads();
        if (wid == 0) {
            int s = (lane < 8) ? wsum[lane] : 0;
#pragma unroll
            for (int o = 4; o > 0; o >>= 1) s += __shfl_down_sync(0xffffffffu, s, o);
            if (lane == 0) off_s = s;
        }
        __syncthreads();
    }
    int offset = off_s;
    __syncthreads();   // protect wsum reuse

    int i = bid * blockDim.x + tid;
    int deg = (i < n) ? g_deg[i] : 1;
    int d = (i < n) ? deg - 1 : 0;

    // inclusive warp scan
    int v = d;
#pragma unroll
    for (int o = 1; o < 32; o <<= 1) {
        int t = __shfl_up_sync(0xffffffffu, v, o);
        if (lane >= o) v += t;
    }
    if (lane == 31) wsum[wid] = v;
    __syncthreads();
    if (wid == 0) {
        int s = (lane < 8) ? wsum[lane] : 0;
#pragma unroll
        for (int o = 1; o < 8; o <<= 1) {
            int t = __shfl_up_sync(0xffffffffu, s, o);
            if (lane >= o) s += t;
        }
        if (lane < 8) wsum[lane] = s;
    }
    __syncthreads();
    int excl = v - d + ((wid > 0) ? wsum[wid - 1] : 0);

    if (i < n) {
        int rp = offset + excl;
        g_rowptr[i] = rp;
        g_pos[i] = rp;
        g_dinv[i] = rsqrtf((float)deg);
    }
    if (i == 0) g_rowptr[n] = e;
}

__global__ void fill_kernel(const void* __restrict__ ei, int e) {
    int i = blockIdx.x * blockDim.x + threadIdx.x;
    if (i < e) {
        int sidx = load_idx(ei, i);
        int d    = load_idx(ei, (long long)e + i);
        g_col[atomicAdd(&g_pos[d], 1)] = sidx;
    }
}

// ---------------- GEMM: g_hp[r][c] = dinv[r] * sum_k X[r][k]*W[k][c] ----------------
// 256 threads/block, 64 rows x 133 cols; K tiled by 32 (static smem < 48KB).
// Thread (warp w, lane l): rows w*8..w*8+7, cols l+32*j (j<5). Scalar FFMA.
__global__ void gemm_scale_kernel(const float* __restrict__ Xext,
                                  const float* __restrict__ W,
                                  int use_ext, int n) {
    __shared__ float Ws[32][DNF + 3];
    __shared__ float Xs[64][33];

    const float* X = use_ext ? Xext : (const float*)g_feat;
    int ldx = use_ext ? DNF : DPAD;
    int tid = threadIdx.x;
    int lane = tid & 31, warp = tid >> 5;
    int row0 = blockIdx.x * 64;
    int rbase = warp * 8;

    float acc[8][5];
#pragma unroll
    for (int i = 0; i < 8; i++)
#pragma unroll
        for (int j = 0; j < 5; j++) acc[i][j] = 0.f;

    for (int k0 = 0; k0 < DNF; k0 += 32) {
        int kc = DNF - k0; if (kc > 32) kc = 32;

        for (int i = tid; i < kc * DNF; i += 256) {
            int kk = i / DNF, c = i - kk * DNF;
            Ws[kk][c] = W[(k0 + kk) * DNF + c];
        }
        for (int i = tid; i < 64 * 32; i += 256) {
            int r = i >> 5, kk = i & 31;
            int gr = row0 + r;
            Xs[r][kk] = (kk < kc && gr < n) ? X[(size_t)gr * ldx + k0 + kk] : 0.f;
        }
        __syncthreads();

        for (int kk = 0; kk < kc; kk++) {
            float b[5];
#pragma unroll
            for (int j = 0; j < 4; j++) b[j] = Ws[kk][lane + 32 * j];
            b[4] = (lane < 5) ? Ws[kk][lane + 128] : 0.f;
#pragma unroll
            for (int i = 0; i < 8; i++) {
                float a = Xs[rbase + i][kk];
#pragma unroll
                for (int j = 0; j < 5; j++) acc[i][j] += a * b[j];
            }
        }
        __syncthreads();
    }

#pragma unroll
    for (int i = 0; i < 8; i++) {
        int r = row0 + rbase + i;
        if (r < n) {
            float di = g_dinv[r];
#pragma unroll
            for (int j = 0; j < 5; j++) {
                int c = lane + 32 * j;
                if (c < DNF) g_hp[(size_t)r * DPAD + c] = acc[i][j] * di;
            }
        }
    }
}

// ---------------- aggregate: g_feat[i] = relu(dinv[i]*(sum_in hp[j] + hp[i]) + b) ----------------
// One warp per node; lane owns float4 at col 4*lane; lanes 0..1 own tail float4s.
__global__ void aggregate_kernel(const float* __restrict__ bias, int n) {
    int node = blockIdx.x * (blockDim.x >> 5) + (threadIdx.x >> 5);
    if (node >= n) return;
    int lane = threadIdx.x & 31;

    const float4* self4 = (const float4*)(g_hp + (size_t)node * DPAD);
    float4 acc = self4[lane];
    float4 acct = make_float4(0.f, 0.f, 0.f, 0.f);
    if (lane < 2) acct = self4[32 + lane];

    int s = g_rowptr[node], e = g_rowptr[node + 1];
    int idx = s;
    for (; idx + 1 < e; idx += 2) {
        int j0 = g_col[idx], j1 = g_col[idx + 1];
        const float4* r0 = (const float4*)(g_hp + (size_t)j0 * DPAD);
        const float4* r1 = (const float4*)(g_hp + (size_t)j1 * DPAD);
        float4 v0 = r0[lane];
        float4 v1 = r1[lane];
        float4 t0, t1;
        if (lane < 2) { t0 = r0[32 + lane]; t1 = r1[32 + lane]; }
        acc.x += v0.x; acc.y += v0.y; acc.z += v0.z; acc.w += v0.w;
        acc.x += v1.x; acc.y += v1.y; acc.z += v1.z; acc.w += v1.w;
        if (lane < 2) {
            acct.x += t0.x; acct.y += t0.y; acct.z += t0.z; acct.w += t0.w;
            acct.x += t1.x; acct.y += t1.y; acct.z += t1.z; acct.w += t1.w;
        }
    }
    if (idx < e) {
        int j0 = g_col[idx];
        const float4* r0 = (const float4*)(g_hp + (size_t)j0 * DPAD);
        float4 v0 = r0[lane];
        acc.x += v0.x; acc.y += v0.y; acc.z += v0.z; acc.w += v0.w;
        if (lane < 2) {
            float4 t0 = r0[32 + lane];
            acct.x += t0.x; acct.y += t0.y; acct.z += t0.z; acct.w += t0.w;
        }
    }

    float di = g_dinv[node];
    float4 o;
    o.x = fmaxf(fmaf(acc.x, di, bias[4 * lane + 0]), 0.f);
    o.y = fmaxf(fmaf(acc.y, di, bias[4 * lane + 1]), 0.f);
    o.z = fmaxf(fmaf(acc.z, di, bias[4 * lane + 2]), 0.f);
    o.w = fmaxf(fmaf(acc.w, di, bias[4 * lane + 3]), 0.f);
    float4* out4 = (float4*)(g_feat + (size_t)node * DPAD);
    out4[lane] = o;
    if (lane == 0) {
        float4 t;
        t.x = fmaxf(fmaf(acct.x, di, bias[128]), 0.f);
        t.y = fmaxf(fmaf(acct.y, di, bias[129]), 0.f);
        t.z = fmaxf(fmaf(acct.z, di, bias[130]), 0.f);
        t.w = fmaxf(fmaf(acct.w, di, bias[131]), 0.f);
        out4[32] = t;
    } else if (lane == 1) {
        float4 t;
        t.x = fmaxf(fmaf(acct.x, di, bias[132]), 0.f);
        t.y = 0.f; t.z = 0.f; t.w = 0.f;   // keep pads zero
        out4[33] = t;
    }
}

// ---------------- global mean pool ----------------
__device__ __forceinline__ int lbound_any(const void* a, int n, int v) {
    int lo = 0, hi = n;
    while (lo < hi) {
        int m = (lo + hi) >> 1;
        long long x = g_is64 ? ((const long long*)a)[m]
                             : (long long)((const int*)a)[m];
        if (x < (long long)v) lo = m + 1; else hi = m;
    }
    return lo;
}

__global__ void pool_kernel(const void* __restrict__ batch,
                            float* __restrict__ out, int n) {
    __shared__ int lo_s, hi_s;
    int g = blockIdx.x;
    if (threadIdx.x == 0) {
        lo_s = lbound_any(batch, n, g);
        hi_s = lbound_any(batch, n, g + 1);
    }
    __syncthreads();
    int lo = lo_s, hi = hi_s;
    int c = threadIdx.x;
    if (c < DNF) {
        float s0 = 0.f, s1 = 0.f, s2 = 0.f, s3 = 0.f;
        int r = lo;
        for (; r + 3 < hi; r += 4) {
            s0 += g_feat[(size_t)(r + 0) * DPAD + c];
            s1 += g_feat[(size_t)(r + 1) * DPAD + c];
            s2 += g_feat[(size_t)(r + 2) * DPAD + c];
            s3 += g_feat[(size_t)(r + 3) * DPAD + c];
        }
        for (; r < hi; r++) s0 += g_feat[(size_t)r * DPAD + c];
        int cnt = hi - lo;
        out[g * DNF + c] = ((s0 + s1) + (s2 + s3)) / (float)(cnt > 0 ? cnt : 1);
    }
}

// ---------------- launch: kernel launches ONLY ----------------
extern "C" void kernel_launch(void* const* d_in, const int* in_sizes, int n_in,
                              void* d_out, int out_size) {
    const float* x     = (const float*)d_in[0];
    const void*  ei    = d_in[1];
    const void*  batch = d_in[2];
    const float* W1    = (const float*)d_in[3];
    const float* b1    = (const float*)d_in[4];
    const float* W2    = (const float*)d_in[5];
    const float* b2    = (const float*)d_in[6];
    float* out = (float*)d_out;

    int n = in_sizes[0] / DNF;   // 50000
    int e = in_sizes[1] / 2;     // 800000

    int tb = 256;
    int gn = (n + tb - 1) / tb;  // 196
    int ge = (e + tb - 1) / tb;

    prologue_kernel<<<gn, tb>>>((const int*)ei, n);   // launch 1: deg=1 + dtype detect
    count_deg_kernel<<<ge, tb>>>(ei, e);              // launch 2
    partial_kernel<<<gn, tb>>>(n);                    // launch 3
    finalize_kernel<<<gn, tb>>>(n, e);                // launch 4: rowptr+pos+dinv
    fill_kernel<<<ge, tb>>>(ei, e);                   // launch 5

    int gemm_blocks = (n + 63) / 64;
    int agg_blocks  = (n + 7) / 8;

    gemm_scale_kernel<<<gemm_blocks, 256>>>(x, W1, 1, n);  // launch 6 <- ncu -s 5 -c 1
    aggregate_kernel<<<agg_blocks, 256>>>(b1, n);
    gemm_scale_kernel<<<gemm_blocks, 256>>>(x, W2, 0, n);
    aggregate_kernel<<<agg_blocks, 256>>>(b2, n);

    pool_kernel<<<NGRAPH, 160>>>(batch, out, n);
}